// round 9
// baseline (speedup 1.0000x reference)
#include <cuda_runtime.h>
#include <cuda_fp16.h>
#include <math.h>
#include <mma.h>
#include <stdint.h>

using namespace nvcuda;

#define MTOK  16384
#define CDIM  768
#define TSEQ  1024
#define BATCH 16
#define NHEAD 8
#define HDIM  96

// ================= scratch (no allocation allowed) =================
__device__ __half g_h  [(size_t)MTOK * CDIM];
__device__ __half g_qkv[(size_t)MTOK * 3 * CDIM];
__device__ __half g_y  [(size_t)MTOK * CDIM];
__device__ float  g_x1 [(size_t)MTOK * CDIM];
__device__ __half g_h2 [(size_t)MTOK * 4 * CDIM];
__device__ __half g_wqkv[(size_t)CDIM * 3 * CDIM];
__device__ __half g_wproj[(size_t)CDIM * CDIM];
__device__ __half g_wfc [(size_t)CDIM * 4 * CDIM];
__device__ __half g_wfc2[(size_t)4 * CDIM * CDIM];

__device__ __forceinline__ float gelu_f(float x) {
    const float x3 = x * x * x;
    return 0.5f * x * (1.0f + tanhf(0.7978845608028654f * (x + 0.044715f * x3)));
}
__device__ __forceinline__ uint32_t smem_u32(const void* p) {
    return (uint32_t)__cvta_generic_to_shared(p);
}
__device__ __forceinline__ void cp16(uint32_t dst, const void* src) {
    asm volatile("cp.async.cg.shared.global [%0], [%1], 16;\n" :: "r"(dst), "l"(src));
}
#define CP_COMMIT() asm volatile("cp.async.commit_group;\n" ::: "memory")
#define CP_WAIT1()  asm volatile("cp.async.wait_group 1;\n" ::: "memory")

// ================= fused weight f32 -> fp16 (all four) =================
__global__ __launch_bounds__(256) void wconv4_kernel(
    const float* __restrict__ s0, __half* __restrict__ d0, int n0,
    const float* __restrict__ s1, __half* __restrict__ d1, int n1,
    const float* __restrict__ s2, __half* __restrict__ d2, int n2,
    const float* __restrict__ s3, __half* __restrict__ d3, int n3)
{
    int i = blockIdx.x * 256 + threadIdx.x;
    const float* src; __half* dst;
    if (i < n0) { src = s0; dst = d0; }
    else if ((i -= n0) < n1) { src = s1; dst = d1; }
    else if ((i -= n1) < n2) { src = s2; dst = d2; }
    else if ((i -= n2) < n3) { src = s3; dst = d3; }
    else return;
    float4 v = ((const float4*)src)[i];
    __half2 a = __floats2half2_rn(v.x, v.y);
    __half2 b = __floats2half2_rn(v.z, v.w);
    *(uint2*)(dst + (size_t)i * 4) = make_uint2(*(uint32_t*)&a, *(uint32_t*)&b);
}

// ================= layernorm (f32 in -> fp16 out) =================
__global__ __launch_bounds__(256) void ln_kernel(
    const float* __restrict__ x, const float* __restrict__ g,
    const float* __restrict__ b, __half* __restrict__ out)
{
    const int row = blockIdx.x;
    const int tid = threadIdx.x;
    const float* xr = x + (size_t)row * CDIM;
    float vals[3];
    float s = 0.f, s2 = 0.f;
#pragma unroll
    for (int j = 0; j < 3; j++) {
        float t = xr[tid + 256 * j];
        vals[j] = t; s += t; s2 += t * t;
    }
#pragma unroll
    for (int o = 16; o > 0; o >>= 1) {
        s  += __shfl_xor_sync(0xffffffffu, s,  o);
        s2 += __shfl_xor_sync(0xffffffffu, s2, o);
    }
    __shared__ float rs[8], rs2[8];
    const int wid = tid >> 5, lane = tid & 31;
    if (lane == 0) { rs[wid] = s; rs2[wid] = s2; }
    __syncthreads();
    s = 0.f; s2 = 0.f;
#pragma unroll
    for (int w = 0; w < 8; w++) { s += rs[w]; s2 += rs2[w]; }
    const float mu  = s * (1.0f / CDIM);
    const float var = s2 * (1.0f / CDIM) - mu * mu;
    const float rstd = rsqrtf(var + 1e-5f);
#pragma unroll
    for (int j = 0; j < 3; j++) {
        const int c = tid + 256 * j;
        out[(size_t)row * CDIM + c] = __float2half_rn((vals[j] - mu) * rstd * g[c] + b[c]);
    }
}

// ================= fp16 tensor-core GEMM, BK=64, 3-stage =================
#define AS_OFF 0
#define BS_OFF (3 * 128 * 72 * 2)
#define STG_OFF (BS_OFF + 3 * 64 * 136 * 2)
#define GEMM_SMEM (STG_OFF + 4 * 16 * 16 * 4)

// EPI: 0 = bias -> half ; 1 = bias+res(f32) -> f32 ; 2 = bias+gelu -> half
template <int EPI>
__global__ __launch_bounds__(128) void hgemm_kernel(
    const __half* __restrict__ A, const __half* __restrict__ B,
    const float* __restrict__ bias, const float* __restrict__ res,
    float* __restrict__ Cf, __half* __restrict__ Ch, int N, int K)
{
    extern __shared__ char dsm[];
    __half* Asb = (__half*)(dsm + AS_OFF);
    __half* Bsb = (__half*)(dsm + BS_OFF);
    float*  stg = (float*)(dsm + STG_OFF);

    const int tid  = threadIdx.x;
    const int wid  = tid >> 5, lane = tid & 31;
    const int wm   = wid >> 1;
    const int wn   = wid & 1;
    const int bx   = blockIdx.x, by = blockIdx.y;

    wmma::fragment<wmma::accumulator, 16, 16, 16, float> c[4][4];
#pragma unroll
    for (int i = 0; i < 4; i++)
#pragma unroll
        for (int j = 0; j < 4; j++) wmma::fill_fragment(c[i][j], 0.0f);

    const __half* Agm = A + (size_t)(by * 128) * K;
    const __half* Bgm = B + bx * 128;
    const int nk = K >> 6;

    const int arb = tid >> 3, ak = (tid & 7) * 8;
    const int bkb = tid >> 4, bc = (tid & 15) * 8;

    auto copy_tile = [&](int s, int kt) {
        const __half* An = Agm + kt * 64;
        const __half* Bn = Bgm + (size_t)(kt * 64) * N;
#pragma unroll
        for (int it = 0; it < 8; it++) {
            const int ar = arb + it * 16;
            const int bk = bkb + it * 8;
            cp16(smem_u32(&Asb[((s * 128) + ar) * 72 + ak]), An + (size_t)ar * K + ak);
            cp16(smem_u32(&Bsb[((s * 64) + bk) * 136 + bc]), Bn + (size_t)bk * N + bc);
        }
    };

    copy_tile(0, 0); CP_COMMIT();
    copy_tile(1, 1); CP_COMMIT();

    int buf = 0, cslot = 2;
    for (int kt = 0; kt < nk; ++kt) {
        CP_WAIT1();
        __syncthreads();
        if (kt + 2 < nk) copy_tile(cslot, kt + 2);
        CP_COMMIT();

#pragma unroll
        for (int ks = 0; ks < 4; ks++) {
            wmma::fragment<wmma::matrix_a, 16, 16, 16, __half, wmma::row_major> a[4];
            wmma::fragment<wmma::matrix_b, 16, 16, 16, __half, wmma::row_major> b[4];
#pragma unroll
            for (int mi = 0; mi < 4; mi++)
                wmma::load_matrix_sync(a[mi],
                    &Asb[((buf * 128) + (wm * 64 + mi * 16)) * 72 + ks * 16], 72);
#pragma unroll
            for (int nj = 0; nj < 4; nj++)
                wmma::load_matrix_sync(b[nj],
                    &Bsb[((buf * 64) + (ks * 16)) * 136 + wn * 64 + nj * 16], 136);
#pragma unroll
            for (int mi = 0; mi < 4; mi++)
#pragma unroll
                for (int nj = 0; nj < 4; nj++)
                    wmma::mma_sync(c[mi][nj], a[mi], b[nj], c[mi][nj]);
        }
        buf   = (buf   == 2) ? 0 : buf + 1;
        cslot = (cslot == 2) ? 0 : cslot + 1;
    }
    __syncthreads();

    const int r  = lane >> 1;
    const int cs = (lane & 1) * 8;
    float* mystg = stg + wid * 256;
#pragma unroll
    for (int mi = 0; mi < 4; mi++) {
#pragma unroll
        for (int nj = 0; nj < 4; nj++) {
            wmma::store_matrix_sync(mystg, c[mi][nj], 16, wmma::mem_row_major);
            __syncwarp();
            const int row = by * 128 + wm * 64 + mi * 16 + r;
            const int col = bx * 128 + wn * 64 + nj * 16 + cs;
            const size_t base = (size_t)row * N + col;
            float4 b0 = *(const float4*)(bias + col);
            float4 b1 = *(const float4*)(bias + col + 4);
            float v[8];
#pragma unroll
            for (int u = 0; u < 8; u++) v[u] = mystg[r * 16 + cs + u];
            v[0] += b0.x; v[1] += b0.y; v[2] += b0.z; v[3] += b0.w;
            v[4] += b1.x; v[5] += b1.y; v[6] += b1.z; v[7] += b1.w;
            if (EPI == 1) {
                float4 r0 = *(const float4*)(res + base);
                float4 r1 = *(const float4*)(res + base + 4);
                v[0] += r0.x; v[1] += r0.y; v[2] += r0.z; v[3] += r0.w;
                v[4] += r1.x; v[5] += r1.y; v[6] += r1.z; v[7] += r1.w;
                *(float4*)(Cf + base)     = make_float4(v[0], v[1], v[2], v[3]);
                *(float4*)(Cf + base + 4) = make_float4(v[4], v[5], v[6], v[7]);
            } else {
                if (EPI == 2) {
#pragma unroll
                    for (int u = 0; u < 8; u++) v[u] = gelu_f(v[u]);
                }
                __half2 h0 = __floats2half2_rn(v[0], v[1]);
                __half2 h1 = __floats2half2_rn(v[2], v[3]);
                __half2 h2 = __floats2half2_rn(v[4], v[5]);
                __half2 h3 = __floats2half2_rn(v[6], v[7]);
                *(uint4*)(Ch + base) = make_uint4(
                    *(uint32_t*)&h0, *(uint32_t*)&h1, *(uint32_t*)&h2, *(uint32_t*)&h3);
            }
            __syncwarp();
        }
    }
}

// ================= fp16 flash attention, 128-key chunks =================
// 64-query tile, 256 threads (8 warps: 4m x 2n over 128 key-cols),
// O in registers, P overlaid on S buffer (row-local within warp).
struct AttnSmem {
    __half Qs[64][104];    // 13312
    __half Ks[128][104];   // 26624  (reused as f32[64][100] output staging)
    __half Vs[128][104];   // 26624
    float  Ss[64][132];    // 33792  (per-row overlaid with half P, stride 264)
    float  fm[64][16];     // 4096
    float  m_s[64], l_s[64];
};

__global__ __launch_bounds__(256) void attn_kernel(
    const __half* __restrict__ qkv, __half* __restrict__ y)
{
    extern __shared__ char smem_raw[];
    AttnSmem& sm = *reinterpret_cast<AttnSmem*>(smem_raw);

    const int qt = blockIdx.x, h = blockIdx.y, b = blockIdx.z;
    const int tid = threadIdx.x;
    const int wid = tid >> 5;
    const int wm = wid >> 1;     // 0..3 : 16-row group
    const int wn = wid & 1;      // 0..1 : 64-key-col half
    const int q0 = qt * 64;
    const float scale = 0.10206207261596575f;

    // ---- load Q tile ----
#pragma unroll
    for (int i = 0; i < 3; i++) {
        const int idx = i * 256 + tid;
        const int row = idx / 12, c = (idx % 12) * 8;
        *(uint4*)&sm.Qs[row][c] =
            *(const uint4*)(qkv + (size_t)(b * TSEQ + q0 + row) * 2304 + h * 96 + c);
    }
    if (tid < 64) { sm.m_s[tid] = -3e38f; sm.l_s[tid] = 0.f; }
    __syncthreads();

    wmma::fragment<wmma::matrix_a, 16, 16, 16, __half, wmma::row_major> qa[6];
#pragma unroll
    for (int ks = 0; ks < 6; ks++)
        wmma::load_matrix_sync(qa[ks], &sm.Qs[wm * 16][ks * 16], 104);
    wmma::fragment<wmma::accumulator, 16, 16, 16, float> oc[3];
#pragma unroll
    for (int j = 0; j < 3; j++) wmma::fill_fragment(oc[j], 0.f);

    const int nch = (qt + 2) >> 1;      // 128-key chunks covering keys [0, q0+64)
    for (int jc = 0; jc < nch; ++jc) {
        const int kb = jc * 128;
        __syncthreads();   // prev PV reads of Ks/Vs/P/fm complete

        // ---- load K/V chunk (128 rows x 96 halfs) ----
#pragma unroll
        for (int i = 0; i < 6; i++) {
            const int idx = i * 256 + tid;
            const int row = idx / 12, c = (idx % 12) * 8;
            const __half* base = qkv + (size_t)(b * TSEQ + kb + row) * 2304 + h * 96 + c;
            *(uint4*)&sm.Ks[row][c] = *(const uint4*)(base + 768);
            *(uint4*)&sm.Vs[row][c] = *(const uint4*)(base + 1536);
        }
        __syncthreads();

        // ---- S = Q K^T  (warp: 16 rows x 64 key-cols) ----
        {
            wmma::fragment<wmma::accumulator, 16, 16, 16, float> sc[4];
#pragma unroll
            for (int j = 0; j < 4; j++) wmma::fill_fragment(sc[j], 0.f);
#pragma unroll
            for (int ks = 0; ks < 6; ks++) {
#pragma unroll
                for (int j = 0; j < 4; j++) {
                    wmma::fragment<wmma::matrix_b, 16, 16, 16, __half, wmma::col_major> bf;
                    wmma::load_matrix_sync(bf, &sm.Ks[wn * 64 + j * 16][ks * 16], 104);
                    wmma::mma_sync(sc[j], qa[ks], bf, sc[j]);
                }
            }
#pragma unroll
            for (int j = 0; j < 4; j++)
                wmma::store_matrix_sync(&sm.Ss[wm * 16][wn * 64 + j * 16], sc[j], 132,
                                        wmma::mem_row_major);
        }
        __syncthreads();

        // ---- online softmax (4 threads/row, interleaved cols c = q4 + 4j) ----
        {
            const int row = tid >> 2;
            const int q4  = tid & 3;
            const int gq  = q0 + row;
            const float m_old = sm.m_s[row];
            float sv[32];
            float mloc = -3e38f;
#pragma unroll
            for (int j = 0; j < 32; j++) {
                const int cc = q4 + j * 4;
                float s = sm.Ss[row][cc] * scale;
                if (kb + cc > gq) s = -3e38f;
                sv[j] = s;
                mloc = fmaxf(mloc, s);
            }
            __syncwarp();   // all S reads of this warp's rows done before P overlay writes
            mloc = fmaxf(mloc, __shfl_xor_sync(0xffffffffu, mloc, 1));
            mloc = fmaxf(mloc, __shfl_xor_sync(0xffffffffu, mloc, 2));
            const float m_new = fmaxf(m_old, mloc);
            float ls = 0.f;
            __half* Pr = (__half*)&sm.Ss[row][0];   // row-local overlay, stride 264 halfs
#pragma unroll
            for (int j = 0; j < 32; j++) {
                const float p = __expf(sv[j] - m_new);
                ls += p;
                Pr[q4 + j * 4] = __float2half_rn(p);
            }
            ls += __shfl_xor_sync(0xffffffffu, ls, 1);
            ls += __shfl_xor_sync(0xffffffffu, ls, 2);
            const float f = __expf(m_old - m_new);
#pragma unroll
            for (int j = 0; j < 4; j++) sm.fm[row][q4 * 4 + j] = f;
            if (q4 == 0) {
                sm.m_s[row] = m_new;
                sm.l_s[row] = sm.l_s[row] * f + ls;
            }
        }
        __syncthreads();

        // ---- rescale O in registers ----
        {
            wmma::fragment<wmma::accumulator, 16, 16, 16, float> F;
            wmma::load_matrix_sync(F, &sm.fm[wm * 16][0], 16, wmma::mem_row_major);
#pragma unroll
            for (int j = 0; j < 3; j++)
#pragma unroll
                for (int e = 0; e < F.num_elements; e++)
                    oc[j].x[e] *= F.x[e];
        }

        // ---- O += P V  (P: 64x128 halfs overlaid on Ss, ldm 264) ----
        const __half* Pb = (const __half*)&sm.Ss[0][0];
#pragma unroll
        for (int ks = 0; ks < 8; ks++) {
            wmma::fragment<wmma::matrix_a, 16, 16, 16, __half, wmma::row_major> pf;
            wmma::load_matrix_sync(pf, Pb + (wm * 16) * 264 + ks * 16, 264);
#pragma unroll
            for (int j = 0; j < 3; j++) {
                wmma::fragment<wmma::matrix_b, 16, 16, 16, __half, wmma::row_major> vf;
                wmma::load_matrix_sync(vf, &sm.Vs[ks * 16][wn * 48 + j * 16], 104);
                wmma::mma_sync(oc[j], pf, vf, oc[j]);
            }
        }
    }
    __syncthreads();

    // ---- final 1/l scaling ----
    {
        const int row = tid >> 2;
        const int q4  = tid & 3;
        const float inv = 1.0f / sm.l_s[row];
#pragma unroll
        for (int j = 0; j < 4; j++) sm.fm[row][q4 * 4 + j] = inv;
    }
    __syncthreads();
    {
        wmma::fragment<wmma::accumulator, 16, 16, 16, float> F;
        wmma::load_matrix_sync(F, &sm.fm[wm * 16][0], 16, wmma::mem_row_major);
#pragma unroll
        for (int j = 0; j < 3; j++)
#pragma unroll
            for (int e = 0; e < F.num_elements; e++)
                oc[j].x[e] *= F.x[e];
    }

    // ---- stage O in (dead) Ks region, write fp16 ----
    float* Ostage = (float*)sm.Ks;   // 64 x 100 f32 = 25.6KB <= 26.6KB
#pragma unroll
    for (int j = 0; j < 3; j++)
        wmma::store_matrix_sync(&Ostage[(wm * 16) * 100 + wn * 48 + j * 16], oc[j], 100,
                                wmma::mem_row_major);
    __syncthreads();
#pragma unroll
    for (int i = 0; i < 6; i++) {
        const int idx = i * 256 + tid;
        const int row = idx / 24, c = idx % 24;
        const float* o = &Ostage[row * 100 + c * 4];
        __half2 h0 = __floats2half2_rn(o[0], o[1]);
        __half2 h1 = __floats2half2_rn(o[2], o[3]);
        *(uint2*)(y + (size_t)(b * TSEQ + q0 + row) * 768 + h * 96 + c * 4) =
            make_uint2(*(uint32_t*)&h0, *(uint32_t*)&h1);
    }
}

// ================= launch =================
extern "C" void kernel_launch(void* const* d_in, const int* in_sizes, int n_in,
                              void* d_out, int out_size)
{
    const float* x      = (const float*)d_in[0];
    const float* ln1_g  = (const float*)d_in[1];
    const float* ln1_b  = (const float*)d_in[2];
    const float* attn_w = (const float*)d_in[3];
    const float* attn_b = (const float*)d_in[4];
    const float* proj_w = (const float*)d_in[5];
    const float* proj_b = (const float*)d_in[6];
    const float* ln2_g  = (const float*)d_in[7];
    const float* ln2_b  = (const float*)d_in[8];
    const float* fc_w   = (const float*)d_in[9];
    const float* fc_b   = (const float*)d_in[10];
    const float* fc2_w  = (const float*)d_in[11];
    const float* fc2_b  = (const float*)d_in[12];
    float* out = (float*)d_out;

    __half *h, *qkv, *y, *h2, *wqkv, *wproj, *wfc, *wfc2;
    float *x1;
    cudaGetSymbolAddress((void**)&h,    g_h);
    cudaGetSymbolAddress((void**)&qkv,  g_qkv);
    cudaGetSymbolAddress((void**)&y,    g_y);
    cudaGetSymbolAddress((void**)&x1,   g_x1);
    cudaGetSymbolAddress((void**)&h2,   g_h2);
    cudaGetSymbolAddress((void**)&wqkv, g_wqkv);
    cudaGetSymbolAddress((void**)&wproj,g_wproj);
    cudaGetSymbolAddress((void**)&wfc,  g_wfc);
    cudaGetSymbolAddress((void**)&wfc2, g_wfc2);

    static bool attr_set = false;
    if (!attr_set) {
        cudaFuncSetAttribute(attn_kernel, cudaFuncAttributeMaxDynamicSharedMemorySize,
                             (int)sizeof(AttnSmem));
        cudaFuncSetAttribute(hgemm_kernel<0>, cudaFuncAttributeMaxDynamicSharedMemorySize, GEMM_SMEM);
        cudaFuncSetAttribute(hgemm_kernel<1>, cudaFuncAttributeMaxDynamicSharedMemorySize, GEMM_SMEM);
        cudaFuncSetAttribute(hgemm_kernel<2>, cudaFuncAttributeMaxDynamicSharedMemorySize, GEMM_SMEM);
        attr_set = true;
    }

    const int n0 = CDIM * 3 * CDIM / 4, n1 = CDIM * CDIM / 4;
    const int n2 = CDIM * 4 * CDIM / 4, n3 = 4 * CDIM * CDIM / 4;
    wconv4_kernel<<<(n0 + n1 + n2 + n3 + 255) / 256, 256>>>(
        attn_w, wqkv, n0, proj_w, wproj, n1, fc_w, wfc, n2, fc2_w, wfc2, n3);

    ln_kernel<<<MTOK, 256>>>(x, ln1_g, ln1_b, h);
    hgemm_kernel<0><<<dim3(2304 / 128, MTOK / 128), 128, GEMM_SMEM>>>(
        h, wqkv, attn_b, nullptr, nullptr, qkv, 2304, 768);
    attn_kernel<<<dim3(TSEQ / 64, NHEAD, BATCH), 256, sizeof(AttnSmem)>>>(qkv, y);
    hgemm_kernel<1><<<dim3(768 / 128, MTOK / 128), 128, GEMM_SMEM>>>(
        y, wproj, proj_b, x, x1, nullptr, 768, 768);
    ln_kernel<<<MTOK, 256>>>(x1, ln2_g, ln2_b, h);
    hgemm_kernel<2><<<dim3(3072 / 128, MTOK / 128), 128, GEMM_SMEM>>>(
        h, wfc, fc_b, nullptr, nullptr, h2, 3072, 768);
    hgemm_kernel<1><<<dim3(768 / 128, MTOK / 128), 128, GEMM_SMEM>>>(
        h2, wfc2, fc2_b, x1, out, nullptr, 768, 3072);
}

// round 10
// speedup vs baseline: 1.1018x; 1.1018x over previous
#include <cuda_runtime.h>
#include <cuda_fp16.h>
#include <math.h>
#include <mma.h>
#include <stdint.h>

using namespace nvcuda;

#define MTOK  16384
#define CDIM  768
#define TSEQ  1024
#define BATCH 16
#define NHEAD 8
#define HDIM  96

// ================= scratch (no allocation allowed) =================
__device__ __half g_h  [(size_t)MTOK * CDIM];
__device__ __half g_qkv[(size_t)MTOK * 3 * CDIM];
__device__ __half g_y  [(size_t)MTOK * CDIM];
__device__ float  g_x1 [(size_t)MTOK * CDIM];
__device__ __half g_h2 [(size_t)MTOK * 4 * CDIM];
__device__ __half g_wqkv[(size_t)CDIM * 3 * CDIM];
__device__ __half g_wproj[(size_t)CDIM * CDIM];
__device__ __half g_wfc [(size_t)CDIM * 4 * CDIM];
__device__ __half g_wfc2[(size_t)4 * CDIM * CDIM];

__device__ __forceinline__ float gelu_f(float x) {
    const float x3 = x * x * x;
    return 0.5f * x * (1.0f + tanhf(0.7978845608028654f * (x + 0.044715f * x3)));
}
__device__ __forceinline__ uint32_t smem_u32(const void* p) {
    return (uint32_t)__cvta_generic_to_shared(p);
}
__device__ __forceinline__ void cp16(uint32_t dst, const void* src) {
    asm volatile("cp.async.cg.shared.global [%0], [%1], 16;\n" :: "r"(dst), "l"(src));
}
#define CP_COMMIT() asm volatile("cp.async.commit_group;\n" ::: "memory")
#define CP_WAIT1()  asm volatile("cp.async.wait_group 1;\n" ::: "memory")

__device__ __forceinline__ void ldsm_x4(
    uint32_t& r0, uint32_t& r1, uint32_t& r2, uint32_t& r3, uint32_t addr)
{
    asm volatile("ldmatrix.sync.aligned.m8n8.x4.shared.b16 {%0,%1,%2,%3}, [%4];"
        : "=r"(r0), "=r"(r1), "=r"(r2), "=r"(r3) : "r"(addr));
}
__device__ __forceinline__ void ldsm_x4_t(
    uint32_t& r0, uint32_t& r1, uint32_t& r2, uint32_t& r3, uint32_t addr)
{
    asm volatile("ldmatrix.sync.aligned.m8n8.x4.trans.shared.b16 {%0,%1,%2,%3}, [%4];"
        : "=r"(r0), "=r"(r1), "=r"(r2), "=r"(r3) : "r"(addr));
}
__device__ __forceinline__ void mma16816(
    float* c, const uint32_t* a, uint32_t b0, uint32_t b1)
{
    asm volatile(
        "mma.sync.aligned.m16n8k16.row.col.f32.f16.f16.f32 "
        "{%0,%1,%2,%3},{%4,%5,%6,%7},{%8,%9},{%0,%1,%2,%3};"
        : "+f"(c[0]), "+f"(c[1]), "+f"(c[2]), "+f"(c[3])
        : "r"(a[0]), "r"(a[1]), "r"(a[2]), "r"(a[3]), "r"(b0), "r"(b1));
}
__device__ __forceinline__ uint32_t packh2(float a, float b) {
    __half2 h = __floats2half2_rn(a, b);
    return *(uint32_t*)&h;
}

// ================= fused weight f32 -> fp16 =================
__global__ __launch_bounds__(256) void wconv4_kernel(
    const float* __restrict__ s0, __half* __restrict__ d0, int n0,
    const float* __restrict__ s1, __half* __restrict__ d1, int n1,
    const float* __restrict__ s2, __half* __restrict__ d2, int n2,
    const float* __restrict__ s3, __half* __restrict__ d3, int n3)
{
    int i = blockIdx.x * 256 + threadIdx.x;
    const float* src; __half* dst;
    if (i < n0) { src = s0; dst = d0; }
    else if ((i -= n0) < n1) { src = s1; dst = d1; }
    else if ((i -= n1) < n2) { src = s2; dst = d2; }
    else if ((i -= n2) < n3) { src = s3; dst = d3; }
    else return;
    float4 v = ((const float4*)src)[i];
    __half2 a = __floats2half2_rn(v.x, v.y);
    __half2 b = __floats2half2_rn(v.z, v.w);
    *(uint2*)(dst + (size_t)i * 4) = make_uint2(*(uint32_t*)&a, *(uint32_t*)&b);
}

// ================= layernorm (f32 in -> fp16 out) =================
__global__ __launch_bounds__(256) void ln_kernel(
    const float* __restrict__ x, const float* __restrict__ g,
    const float* __restrict__ b, __half* __restrict__ out)
{
    const int row = blockIdx.x;
    const int tid = threadIdx.x;
    const float* xr = x + (size_t)row * CDIM;
    float vals[3];
    float s = 0.f, s2 = 0.f;
#pragma unroll
    for (int j = 0; j < 3; j++) {
        float t = xr[tid + 256 * j];
        vals[j] = t; s += t; s2 += t * t;
    }
#pragma unroll
    for (int o = 16; o > 0; o >>= 1) {
        s  += __shfl_xor_sync(0xffffffffu, s,  o);
        s2 += __shfl_xor_sync(0xffffffffu, s2, o);
    }
    __shared__ float rs[8], rs2[8];
    const int wid = tid >> 5, lane = tid & 31;
    if (lane == 0) { rs[wid] = s; rs2[wid] = s2; }
    __syncthreads();
    s = 0.f; s2 = 0.f;
#pragma unroll
    for (int w = 0; w < 8; w++) { s += rs[w]; s2 += rs2[w]; }
    const float mu  = s * (1.0f / CDIM);
    const float var = s2 * (1.0f / CDIM) - mu * mu;
    const float rstd = rsqrtf(var + 1e-5f);
#pragma unroll
    for (int j = 0; j < 3; j++) {
        const int c = tid + 256 * j;
        out[(size_t)row * CDIM + c] = __float2half_rn((vals[j] - mu) * rstd * g[c] + b[c]);
    }
}

// ================= fp16 tensor-core GEMM, BK=64, 3-stage =================
#define AS_OFF 0
#define BS_OFF (3 * 128 * 72 * 2)
#define STG_OFF (BS_OFF + 3 * 64 * 136 * 2)
#define GEMM_SMEM (STG_OFF + 4 * 16 * 16 * 4)

template <int EPI>
__global__ __launch_bounds__(128) void hgemm_kernel(
    const __half* __restrict__ A, const __half* __restrict__ B,
    const float* __restrict__ bias, const float* __restrict__ res,
    float* __restrict__ Cf, __half* __restrict__ Ch, int N, int K)
{
    extern __shared__ char dsm[];
    __half* Asb = (__half*)(dsm + AS_OFF);
    __half* Bsb = (__half*)(dsm + BS_OFF);
    float*  stg = (float*)(dsm + STG_OFF);

    const int tid  = threadIdx.x;
    const int wid  = tid >> 5, lane = tid & 31;
    const int wm   = wid >> 1;
    const int wn   = wid & 1;
    const int bx   = blockIdx.x, by = blockIdx.y;

    wmma::fragment<wmma::accumulator, 16, 16, 16, float> c[4][4];
#pragma unroll
    for (int i = 0; i < 4; i++)
#pragma unroll
        for (int j = 0; j < 4; j++) wmma::fill_fragment(c[i][j], 0.0f);

    const __half* Agm = A + (size_t)(by * 128) * K;
    const __half* Bgm = B + bx * 128;
    const int nk = K >> 6;

    const int arb = tid >> 3, ak = (tid & 7) * 8;
    const int bkb = tid >> 4, bc = (tid & 15) * 8;

    auto copy_tile = [&](int s, int kt) {
        const __half* An = Agm + kt * 64;
        const __half* Bn = Bgm + (size_t)(kt * 64) * N;
#pragma unroll
        for (int it = 0; it < 8; it++) {
            const int ar = arb + it * 16;
            const int bk = bkb + it * 8;
            cp16(smem_u32(&Asb[((s * 128) + ar) * 72 + ak]), An + (size_t)ar * K + ak);
            cp16(smem_u32(&Bsb[((s * 64) + bk) * 136 + bc]), Bn + (size_t)bk * N + bc);
        }
    };

    copy_tile(0, 0); CP_COMMIT();
    copy_tile(1, 1); CP_COMMIT();

    int buf = 0, cslot = 2;
    for (int kt = 0; kt < nk; ++kt) {
        CP_WAIT1();
        __syncthreads();
        if (kt + 2 < nk) copy_tile(cslot, kt + 2);
        CP_COMMIT();

#pragma unroll
        for (int ks = 0; ks < 4; ks++) {
            wmma::fragment<wmma::matrix_a, 16, 16, 16, __half, wmma::row_major> a[4];
            wmma::fragment<wmma::matrix_b, 16, 16, 16, __half, wmma::row_major> b[4];
#pragma unroll
            for (int mi = 0; mi < 4; mi++)
                wmma::load_matrix_sync(a[mi],
                    &Asb[((buf * 128) + (wm * 64 + mi * 16)) * 72 + ks * 16], 72);
#pragma unroll
            for (int nj = 0; nj < 4; nj++)
                wmma::load_matrix_sync(b[nj],
                    &Bsb[((buf * 64) + (ks * 16)) * 136 + wn * 64 + nj * 16], 136);
#pragma unroll
            for (int mi = 0; mi < 4; mi++)
#pragma unroll
                for (int nj = 0; nj < 4; nj++)
                    wmma::mma_sync(c[mi][nj], a[mi], b[nj], c[mi][nj]);
        }
        buf   = (buf   == 2) ? 0 : buf + 1;
        cslot = (cslot == 2) ? 0 : cslot + 1;
    }
    __syncthreads();

    const int r  = lane >> 1;
    const int cs = (lane & 1) * 8;
    float* mystg = stg + wid * 256;
#pragma unroll
    for (int mi = 0; mi < 4; mi++) {
#pragma unroll
        for (int nj = 0; nj < 4; nj++) {
            wmma::store_matrix_sync(mystg, c[mi][nj], 16, wmma::mem_row_major);
            __syncwarp();
            const int row = by * 128 + wm * 64 + mi * 16 + r;
            const int col = bx * 128 + wn * 64 + nj * 16 + cs;
            const size_t base = (size_t)row * N + col;
            float4 b0 = *(const float4*)(bias + col);
            float4 b1 = *(const float4*)(bias + col + 4);
            float v[8];
#pragma unroll
            for (int u = 0; u < 8; u++) v[u] = mystg[r * 16 + cs + u];
            v[0] += b0.x; v[1] += b0.y; v[2] += b0.z; v[3] += b0.w;
            v[4] += b1.x; v[5] += b1.y; v[6] += b1.z; v[7] += b1.w;
            if (EPI == 1) {
                float4 r0 = *(const float4*)(res + base);
                float4 r1 = *(const float4*)(res + base + 4);
                v[0] += r0.x; v[1] += r0.y; v[2] += r0.z; v[3] += r0.w;
                v[4] += r1.x; v[5] += r1.y; v[6] += r1.z; v[7] += r1.w;
                *(float4*)(Cf + base)     = make_float4(v[0], v[1], v[2], v[3]);
                *(float4*)(Cf + base + 4) = make_float4(v[4], v[5], v[6], v[7]);
            } else {
                if (EPI == 2) {
#pragma unroll
                    for (int u = 0; u < 8; u++) v[u] = gelu_f(v[u]);
                }
                __half2 h0 = __floats2half2_rn(v[0], v[1]);
                __half2 h1 = __floats2half2_rn(v[2], v[3]);
                __half2 h2 = __floats2half2_rn(v[4], v[5]);
                __half2 h3 = __floats2half2_rn(v[6], v[7]);
                *(uint4*)(Ch + base) = make_uint4(
                    *(uint32_t*)&h0, *(uint32_t*)&h1, *(uint32_t*)&h2, *(uint32_t*)&h3);
            }
            __syncwarp();
        }
    }
}

// ================= FA2-style attention: mma.sync + in-register softmax ======
// 64-query tile, 128 threads (4 warps; warp w owns rows w*16..w*16+15),
// 64-key chunks, S/P/m/l in registers, Q/K/V only in smem.
struct AttnSmem {
    __half Qs[64][104];
    __half Ks[64][104];
    __half Vs[64][104];
};

__global__ __launch_bounds__(128, 3) void attn_kernel(
    const __half* __restrict__ qkv, __half* __restrict__ y)
{
    __shared__ AttnSmem sm;
    const int qt = blockIdx.x, h = blockIdx.y, b = blockIdx.z;
    const int tid = threadIdx.x;
    const int w = tid >> 5, lane = tid & 31;
    const int g = lane >> 2, q4 = lane & 3;
    const int grp = lane >> 3, lr = lane & 7;
    const int q0 = qt * 64;
    const float scale = 0.10206207261596575f;

    // ---- load Q tile ----
#pragma unroll
    for (int i = 0; i < 6; i++) {
        const int idx = i * 128 + tid;
        const int row = idx / 12, c = (idx % 12) * 8;
        *(uint4*)&sm.Qs[row][c] =
            *(const uint4*)(qkv + (size_t)(b * TSEQ + q0 + row) * 2304 + h * 96 + c);
    }
    __syncthreads();

    // ---- Q a-frags (m16k16), 6 k-tiles ----
    uint32_t qa[6][4];
#pragma unroll
    for (int k = 0; k < 6; k++) {
        const int row = w * 16 + ((grp & 1) ? 8 : 0) + lr;
        const int col = k * 16 + ((grp & 2) ? 8 : 0);
        ldsm_x4(qa[k][0], qa[k][1], qa[k][2], qa[k][3], smem_u32(&sm.Qs[row][col]));
    }

    float oc[12][4];
#pragma unroll
    for (int j = 0; j < 12; j++)
#pragma unroll
        for (int e = 0; e < 4; e++) oc[j][e] = 0.f;
    float m0 = -3e38f, m1 = -3e38f, l0 = 0.f, l1 = 0.f;

    const int row0 = q0 + w * 16 + g;
    const int row1 = row0 + 8;

    for (int jc = 0; jc <= qt; ++jc) {
        const int kb = jc * 64;
        __syncthreads();   // prev chunk's mma reads of Ks/Vs done

        // ---- load K/V chunk ----
#pragma unroll
        for (int i = 0; i < 6; i++) {
            const int idx = i * 128 + tid;
            const int row = idx / 12, c = (idx % 12) * 8;
            const __half* base = qkv + (size_t)(b * TSEQ + kb + row) * 2304 + h * 96 + c;
            *(uint4*)&sm.Ks[row][c] = *(const uint4*)(base + 768);
            *(uint4*)&sm.Vs[row][c] = *(const uint4*)(base + 1536);
        }
        __syncthreads();

        // ---- S = Q K^T : 8 n8-tiles in registers ----
        float sc[8][4];
#pragma unroll
        for (int j = 0; j < 8; j++)
#pragma unroll
            for (int e = 0; e < 4; e++) sc[j][e] = 0.f;
#pragma unroll
        for (int k = 0; k < 6; k++) {
#pragma unroll
            for (int jn = 0; jn < 4; jn++) {
                const int key = jn * 16 + lr + ((grp & 2) ? 8 : 0);
                const int hd  = k * 16 + ((grp & 1) ? 8 : 0);
                uint32_t b0, b1, b2, b3;
                ldsm_x4(b0, b1, b2, b3, smem_u32(&sm.Ks[key][hd]));
                mma16816(sc[2 * jn],     qa[k], b0, b1);
                mma16816(sc[2 * jn + 1], qa[k], b2, b3);
            }
        }

        // ---- mask + scale + row max (registers + quad shuffles) ----
        const bool diag = (jc == qt);
        float mloc0 = -3e38f, mloc1 = -3e38f;
#pragma unroll
        for (int j = 0; j < 8; j++) {
            const int c0 = kb + j * 8 + q4 * 2;
            sc[j][0] *= scale; sc[j][1] *= scale;
            sc[j][2] *= scale; sc[j][3] *= scale;
            if (diag) {
                if (c0     > row0) sc[j][0] = -3e38f;
                if (c0 + 1 > row0) sc[j][1] = -3e38f;
                if (c0     > row1) sc[j][2] = -3e38f;
                if (c0 + 1 > row1) sc[j][3] = -3e38f;
            }
            mloc0 = fmaxf(mloc0, fmaxf(sc[j][0], sc[j][1]));
            mloc1 = fmaxf(mloc1, fmaxf(sc[j][2], sc[j][3]));
        }
        mloc0 = fmaxf(mloc0, __shfl_xor_sync(0xffffffffu, mloc0, 1));
        mloc0 = fmaxf(mloc0, __shfl_xor_sync(0xffffffffu, mloc0, 2));
        mloc1 = fmaxf(mloc1, __shfl_xor_sync(0xffffffffu, mloc1, 1));
        mloc1 = fmaxf(mloc1, __shfl_xor_sync(0xffffffffu, mloc1, 2));
        const float m0n = fmaxf(m0, mloc0);
        const float m1n = fmaxf(m1, mloc1);
        const float f0 = __expf(m0 - m0n);
        const float f1 = __expf(m1 - m1n);
        m0 = m0n; m1 = m1n;

        // ---- P = exp(S - m), packed directly into a-frags ----
        uint32_t pa[4][4];
        float ls0 = 0.f, ls1 = 0.f;
#pragma unroll
        for (int k = 0; k < 4; k++) {
            const float pA0 = __expf(sc[2 * k][0] - m0);
            const float pA1 = __expf(sc[2 * k][1] - m0);
            const float pA2 = __expf(sc[2 * k][2] - m1);
            const float pA3 = __expf(sc[2 * k][3] - m1);
            const float pB0 = __expf(sc[2 * k + 1][0] - m0);
            const float pB1 = __expf(sc[2 * k + 1][1] - m0);
            const float pB2 = __expf(sc[2 * k + 1][2] - m1);
            const float pB3 = __expf(sc[2 * k + 1][3] - m1);
            ls0 += pA0 + pA1 + pB0 + pB1;
            ls1 += pA2 + pA3 + pB2 + pB3;
            pa[k][0] = packh2(pA0, pA1);   // row g,   keys k*16 + q4*2 +{0,1}
            pa[k][1] = packh2(pA2, pA3);   // row g+8, same keys
            pa[k][2] = packh2(pB0, pB1);   // row g,   keys +8
            pa[k][3] = packh2(pB2, pB3);   // row g+8, keys +8
        }
        ls0 += __shfl_xor_sync(0xffffffffu, ls0, 1);
        ls0 += __shfl_xor_sync(0xffffffffu, ls0, 2);
        ls1 += __shfl_xor_sync(0xffffffffu, ls1, 1);
        ls1 += __shfl_xor_sync(0xffffffffu, ls1, 2);
        l0 = l0 * f0 + ls0;
        l1 = l1 * f1 + ls1;

        // ---- rescale O (registers) ----
#pragma unroll
        for (int j = 0; j < 12; j++) {
            oc[j][0] *= f0; oc[j][1] *= f0;
            oc[j][2] *= f1; oc[j][3] *= f1;
        }

        // ---- O += P V ----
#pragma unroll
        for (int n = 0; n < 6; n++) {
#pragma unroll
            for (int k = 0; k < 4; k++) {
                const int key = k * 16 + lr + ((grp & 1) ? 8 : 0);
                const int hd  = n * 16 + ((grp & 2) ? 8 : 0);
                uint32_t b0, b1, b2, b3;
                ldsm_x4_t(b0, b1, b2, b3, smem_u32(&sm.Vs[key][hd]));
                mma16816(oc[2 * n],     pa[k], b0, b1);
                mma16816(oc[2 * n + 1], pa[k], b2, b3);
            }
        }
    }

    // ---- write y = O / l directly from registers ----
    const float inv0 = 1.0f / l0;
    const float inv1 = 1.0f / l1;
    __half* y0 = y + (size_t)(b * TSEQ + row0) * 768 + h * 96;
    __half* y1 = y + (size_t)(b * TSEQ + row1) * 768 + h * 96;
#pragma unroll
    for (int j = 0; j < 12; j++) {
        const int col = j * 8 + q4 * 2;
        const uint32_t h0 = packh2(oc[j][0] * inv0, oc[j][1] * inv0);
        const uint32_t h1 = packh2(oc[j][2] * inv1, oc[j][3] * inv1);
        *(uint32_t*)(y0 + col) = h0;
        *(uint32_t*)(y1 + col) = h1;
    }
}

// ================= launch =================
extern "C" void kernel_launch(void* const* d_in, const int* in_sizes, int n_in,
                              void* d_out, int out_size)
{
    const float* x      = (const float*)d_in[0];
    const float* ln1_g  = (const float*)d_in[1];
    const float* ln1_b  = (const float*)d_in[2];
    const float* attn_w = (const float*)d_in[3];
    const float* attn_b = (const float*)d_in[4];
    const float* proj_w = (const float*)d_in[5];
    const float* proj_b = (const float*)d_in[6];
    const float* ln2_g  = (const float*)d_in[7];
    const float* ln2_b  = (const float*)d_in[8];
    const float* fc_w   = (const float*)d_in[9];
    const float* fc_b   = (const float*)d_in[10];
    const float* fc2_w  = (const float*)d_in[11];
    const float* fc2_b  = (const float*)d_in[12];
    float* out = (float*)d_out;

    __half *h, *qkv, *y, *h2, *wqkv, *wproj, *wfc, *wfc2;
    float *x1;
    cudaGetSymbolAddress((void**)&h,    g_h);
    cudaGetSymbolAddress((void**)&qkv,  g_qkv);
    cudaGetSymbolAddress((void**)&y,    g_y);
    cudaGetSymbolAddress((void**)&x1,   g_x1);
    cudaGetSymbolAddress((void**)&h2,   g_h2);
    cudaGetSymbolAddress((void**)&wqkv, g_wqkv);
    cudaGetSymbolAddress((void**)&wproj,g_wproj);
    cudaGetSymbolAddress((void**)&wfc,  g_wfc);
    cudaGetSymbolAddress((void**)&wfc2, g_wfc2);

    static bool attr_set = false;
    if (!attr_set) {
        cudaFuncSetAttribute(hgemm_kernel<0>, cudaFuncAttributeMaxDynamicSharedMemorySize, GEMM_SMEM);
        cudaFuncSetAttribute(hgemm_kernel<1>, cudaFuncAttributeMaxDynamicSharedMemorySize, GEMM_SMEM);
        cudaFuncSetAttribute(hgemm_kernel<2>, cudaFuncAttributeMaxDynamicSharedMemorySize, GEMM_SMEM);
        attr_set = true;
    }

    const int n0 = CDIM * 3 * CDIM / 4, n1 = CDIM * CDIM / 4;
    const int n2 = CDIM * 4 * CDIM / 4, n3 = 4 * CDIM * CDIM / 4;
    wconv4_kernel<<<(n0 + n1 + n2 + n3 + 255) / 256, 256>>>(
        attn_w, wqkv, n0, proj_w, wproj, n1, fc_w, wfc, n2, fc2_w, wfc2, n3);

    ln_kernel<<<MTOK, 256>>>(x, ln1_g, ln1_b, h);
    hgemm_kernel<0><<<dim3(2304 / 128, MTOK / 128), 128, GEMM_SMEM>>>(
        h, wqkv, attn_b, nullptr, nullptr, qkv, 2304, 768);
    attn_kernel<<<dim3(TSEQ / 64, NHEAD, BATCH), 128>>>(qkv, y);
    hgemm_kernel<1><<<dim3(768 / 128, MTOK / 128), 128, GEMM_SMEM>>>(
        y, wproj, proj_b, x, x1, nullptr, 768, 768);
    ln_kernel<<<MTOK, 256>>>(x1, ln2_g, ln2_b, h);
    hgemm_kernel<2><<<dim3(3072 / 128, MTOK / 128), 128, GEMM_SMEM>>>(
        h, wfc, fc_b, nullptr, nullptr, h2, 3072, 768);
    hgemm_kernel<1><<<dim3(768 / 128, MTOK / 128), 128, GEMM_SMEM>>>(
        h2, wfc2, fc2_b, x1, out, nullptr, 768, 3072);
}

// round 11
// speedup vs baseline: 1.1047x; 1.0026x over previous
#include <cuda_runtime.h>
#include <cuda_fp16.h>
#include <math.h>
#include <mma.h>
#include <stdint.h>

using namespace nvcuda;

#define MTOK  16384
#define CDIM  768
#define TSEQ  1024
#define BATCH 16
#define NHEAD 8
#define HDIM  96

// ================= scratch (no allocation allowed) =================
__device__ __half g_h  [(size_t)MTOK * CDIM];
__device__ __half g_qkv[(size_t)MTOK * 3 * CDIM];
__device__ __half g_y  [(size_t)MTOK * CDIM];
__device__ float  g_x1 [(size_t)MTOK * CDIM];
__device__ __half g_h2 [(size_t)MTOK * 4 * CDIM];
__device__ __half g_wqkv[(size_t)CDIM * 3 * CDIM];
__device__ __half g_wproj[(size_t)CDIM * CDIM];
__device__ __half g_wfc [(size_t)CDIM * 4 * CDIM];
__device__ __half g_wfc2[(size_t)4 * CDIM * CDIM];

__device__ __forceinline__ float gelu_f(float x) {
    const float x3 = x * x * x;
    return 0.5f * x * (1.0f + tanhf(0.7978845608028654f * (x + 0.044715f * x3)));
}
__device__ __forceinline__ uint32_t smem_u32(const void* p) {
    return (uint32_t)__cvta_generic_to_shared(p);
}
__device__ __forceinline__ void cp16(uint32_t dst, const void* src) {
    asm volatile("cp.async.cg.shared.global [%0], [%1], 16;\n" :: "r"(dst), "l"(src));
}
#define CP_COMMIT() asm volatile("cp.async.commit_group;\n" ::: "memory")
#define CP_WAIT1()  asm volatile("cp.async.wait_group 1;\n" ::: "memory")

__device__ __forceinline__ void ldsm_x4(
    uint32_t& r0, uint32_t& r1, uint32_t& r2, uint32_t& r3, uint32_t addr)
{
    asm volatile("ldmatrix.sync.aligned.m8n8.x4.shared.b16 {%0,%1,%2,%3}, [%4];"
        : "=r"(r0), "=r"(r1), "=r"(r2), "=r"(r3) : "r"(addr));
}
__device__ __forceinline__ void ldsm_x4_t(
    uint32_t& r0, uint32_t& r1, uint32_t& r2, uint32_t& r3, uint32_t addr)
{
    asm volatile("ldmatrix.sync.aligned.m8n8.x4.trans.shared.b16 {%0,%1,%2,%3}, [%4];"
        : "=r"(r0), "=r"(r1), "=r"(r2), "=r"(r3) : "r"(addr));
}
__device__ __forceinline__ void mma16816(
    float* c, const uint32_t* a, uint32_t b0, uint32_t b1)
{
    asm volatile(
        "mma.sync.aligned.m16n8k16.row.col.f32.f16.f16.f32 "
        "{%0,%1,%2,%3},{%4,%5,%6,%7},{%8,%9},{%0,%1,%2,%3};"
        : "+f"(c[0]), "+f"(c[1]), "+f"(c[2]), "+f"(c[3])
        : "r"(a[0]), "r"(a[1]), "r"(a[2]), "r"(a[3]), "r"(b0), "r"(b1));
}
__device__ __forceinline__ uint32_t packh2(float a, float b) {
    __half2 h = __floats2half2_rn(a, b);
    return *(uint32_t*)&h;
}

// ================= fused weight f32 -> fp16 =================
__global__ __launch_bounds__(256) void wconv4_kernel(
    const float* __restrict__ s0, __half* __restrict__ d0, int n0,
    const float* __restrict__ s1, __half* __restrict__ d1, int n1,
    const float* __restrict__ s2, __half* __restrict__ d2, int n2,
    const float* __restrict__ s3, __half* __restrict__ d3, int n3)
{
    int i = blockIdx.x * 256 + threadIdx.x;
    const float* src; __half* dst;
    if (i < n0) { src = s0; dst = d0; }
    else if ((i -= n0) < n1) { src = s1; dst = d1; }
    else if ((i -= n1) < n2) { src = s2; dst = d2; }
    else if ((i -= n2) < n3) { src = s3; dst = d3; }
    else return;
    float4 v = ((const float4*)src)[i];
    __half2 a = __floats2half2_rn(v.x, v.y);
    __half2 b = __floats2half2_rn(v.z, v.w);
    *(uint2*)(dst + (size_t)i * 4) = make_uint2(*(uint32_t*)&a, *(uint32_t*)&b);
}

// ================= layernorm (f32 in -> fp16 out) =================
__global__ __launch_bounds__(256) void ln_kernel(
    const float* __restrict__ x, const float* __restrict__ g,
    const float* __restrict__ b, __half* __restrict__ out)
{
    const int row = blockIdx.x;
    const int tid = threadIdx.x;
    const float* xr = x + (size_t)row * CDIM;
    float vals[3];
    float s = 0.f, s2 = 0.f;
#pragma unroll
    for (int j = 0; j < 3; j++) {
        float t = xr[tid + 256 * j];
        vals[j] = t; s += t; s2 += t * t;
    }
#pragma unroll
    for (int o = 16; o > 0; o >>= 1) {
        s  += __shfl_xor_sync(0xffffffffu, s,  o);
        s2 += __shfl_xor_sync(0xffffffffu, s2, o);
    }
    __shared__ float rs[8], rs2[8];
    const int wid = tid >> 5, lane = tid & 31;
    if (lane == 0) { rs[wid] = s; rs2[wid] = s2; }
    __syncthreads();
    s = 0.f; s2 = 0.f;
#pragma unroll
    for (int w = 0; w < 8; w++) { s += rs[w]; s2 += rs2[w]; }
    const float mu  = s * (1.0f / CDIM);
    const float var = s2 * (1.0f / CDIM) - mu * mu;
    const float rstd = rsqrtf(var + 1e-5f);
#pragma unroll
    for (int j = 0; j < 3; j++) {
        const int c = tid + 256 * j;
        out[(size_t)row * CDIM + c] = __float2half_rn((vals[j] - mu) * rstd * g[c] + b[c]);
    }
}

// ================= fp16 tensor-core GEMM, BK=64, 3-stage =================
#define AS_OFF 0
#define BS_OFF (3 * 128 * 72 * 2)
#define STG_OFF (BS_OFF + 3 * 64 * 136 * 2)
#define GEMM_SMEM (STG_OFF + 4 * 16 * 16 * 4)

template <int EPI>
__global__ __launch_bounds__(128) void hgemm_kernel(
    const __half* __restrict__ A, const __half* __restrict__ B,
    const float* __restrict__ bias, const float* __restrict__ res,
    float* __restrict__ Cf, __half* __restrict__ Ch, int N, int K)
{
    extern __shared__ char dsm[];
    __half* Asb = (__half*)(dsm + AS_OFF);
    __half* Bsb = (__half*)(dsm + BS_OFF);
    float*  stg = (float*)(dsm + STG_OFF);

    const int tid  = threadIdx.x;
    const int wid  = tid >> 5, lane = tid & 31;
    const int wm   = wid >> 1;
    const int wn   = wid & 1;
    const int bx   = blockIdx.x, by = blockIdx.y;

    wmma::fragment<wmma::accumulator, 16, 16, 16, float> c[4][4];
#pragma unroll
    for (int i = 0; i < 4; i++)
#pragma unroll
        for (int j = 0; j < 4; j++) wmma::fill_fragment(c[i][j], 0.0f);

    const __half* Agm = A + (size_t)(by * 128) * K;
    const __half* Bgm = B + bx * 128;
    const int nk = K >> 6;

    const int arb = tid >> 3, ak = (tid & 7) * 8;
    const int bkb = tid >> 4, bc = (tid & 15) * 8;

    auto copy_tile = [&](int s, int kt) {
        const __half* An = Agm + kt * 64;
        const __half* Bn = Bgm + (size_t)(kt * 64) * N;
#pragma unroll
        for (int it = 0; it < 8; it++) {
            const int ar = arb + it * 16;
            const int bk = bkb + it * 8;
            cp16(smem_u32(&Asb[((s * 128) + ar) * 72 + ak]), An + (size_t)ar * K + ak);
            cp16(smem_u32(&Bsb[((s * 64) + bk) * 136 + bc]), Bn + (size_t)bk * N + bc);
        }
    };

    copy_tile(0, 0); CP_COMMIT();
    copy_tile(1, 1); CP_COMMIT();

    int buf = 0, cslot = 2;
    for (int kt = 0; kt < nk; ++kt) {
        CP_WAIT1();
        __syncthreads();
        if (kt + 2 < nk) copy_tile(cslot, kt + 2);
        CP_COMMIT();

#pragma unroll
        for (int ks = 0; ks < 4; ks++) {
            wmma::fragment<wmma::matrix_a, 16, 16, 16, __half, wmma::row_major> a[4];
            wmma::fragment<wmma::matrix_b, 16, 16, 16, __half, wmma::row_major> b[4];
#pragma unroll
            for (int mi = 0; mi < 4; mi++)
                wmma::load_matrix_sync(a[mi],
                    &Asb[((buf * 128) + (wm * 64 + mi * 16)) * 72 + ks * 16], 72);
#pragma unroll
            for (int nj = 0; nj < 4; nj++)
                wmma::load_matrix_sync(b[nj],
                    &Bsb[((buf * 64) + (ks * 16)) * 136 + wn * 64 + nj * 16], 136);
#pragma unroll
            for (int mi = 0; mi < 4; mi++)
#pragma unroll
                for (int nj = 0; nj < 4; nj++)
                    wmma::mma_sync(c[mi][nj], a[mi], b[nj], c[mi][nj]);
        }
        buf   = (buf   == 2) ? 0 : buf + 1;
        cslot = (cslot == 2) ? 0 : cslot + 1;
    }
    __syncthreads();

    const int r  = lane >> 1;
    const int cs = (lane & 1) * 8;
    float* mystg = stg + wid * 256;
#pragma unroll
    for (int mi = 0; mi < 4; mi++) {
#pragma unroll
        for (int nj = 0; nj < 4; nj++) {
            wmma::store_matrix_sync(mystg, c[mi][nj], 16, wmma::mem_row_major);
            __syncwarp();
            const int row = by * 128 + wm * 64 + mi * 16 + r;
            const int col = bx * 128 + wn * 64 + nj * 16 + cs;
            const size_t base = (size_t)row * N + col;
            float4 b0 = *(const float4*)(bias + col);
            float4 b1 = *(const float4*)(bias + col + 4);
            float v[8];
#pragma unroll
            for (int u = 0; u < 8; u++) v[u] = mystg[r * 16 + cs + u];
            v[0] += b0.x; v[1] += b0.y; v[2] += b0.z; v[3] += b0.w;
            v[4] += b1.x; v[5] += b1.y; v[6] += b1.z; v[7] += b1.w;
            if (EPI == 1) {
                float4 r0 = *(const float4*)(res + base);
                float4 r1 = *(const float4*)(res + base + 4);
                v[0] += r0.x; v[1] += r0.y; v[2] += r0.z; v[3] += r0.w;
                v[4] += r1.x; v[5] += r1.y; v[6] += r1.z; v[7] += r1.w;
                *(float4*)(Cf + base)     = make_float4(v[0], v[1], v[2], v[3]);
                *(float4*)(Cf + base + 4) = make_float4(v[4], v[5], v[6], v[7]);
            } else {
                if (EPI == 2) {
#pragma unroll
                    for (int u = 0; u < 8; u++) v[u] = gelu_f(v[u]);
                }
                __half2 h0 = __floats2half2_rn(v[0], v[1]);
                __half2 h1 = __floats2half2_rn(v[2], v[3]);
                __half2 h2 = __floats2half2_rn(v[4], v[5]);
                __half2 h3 = __floats2half2_rn(v[6], v[7]);
                *(uint4*)(Ch + base) = make_uint4(
                    *(uint32_t*)&h0, *(uint32_t*)&h1, *(uint32_t*)&h2, *(uint32_t*)&h3);
            }
            __syncwarp();
        }
    }
}

// ================= FA2 attention: 32 query rows per warp =================
// 128-query tile, 128 threads (4 warps; warp w owns rows w*32..w*32+31 as
// two m16 tiles), 64-key chunks processed as two 32-key subtiles.
// S/P/m/l in registers; K/V fragments amortized over both m-tiles.
#define ATTN_SMEM ((128 + 64 + 64) * 104 * 2)

__global__ __launch_bounds__(128) void attn_kernel(
    const __half* __restrict__ qkv, __half* __restrict__ y)
{
    extern __shared__ __half asm_[];
    __half* Qs = asm_;                 // [128][104]
    __half* Ks = asm_ + 128 * 104;     // [64][104]
    __half* Vs = asm_ + 192 * 104;     // [64][104]

    const int qt = blockIdx.x, h = blockIdx.y, b = blockIdx.z;
    const int tid = threadIdx.x;
    const int w = tid >> 5, lane = tid & 31;
    const int g = lane >> 2, q4 = lane & 3;
    const int grp = lane >> 3, lr = lane & 7;
    const int q0 = qt * 128;
    const float scale = 0.10206207261596575f;

    // ---- load Q tile (128 rows x 96 halfs = 1536 uint4) ----
#pragma unroll
    for (int i = 0; i < 12; i++) {
        const int idx = i * 128 + tid;
        const int row = idx / 12, c = (idx % 12) * 8;
        *(uint4*)&Qs[row * 104 + c] =
            *(const uint4*)(qkv + (size_t)(b * TSEQ + q0 + row) * 2304 + h * 96 + c);
    }
    __syncthreads();

    // ---- Q a-frags: 2 m-tiles x 6 k-tiles ----
    uint32_t qa[2][6][4];
#pragma unroll
    for (int mi = 0; mi < 2; mi++)
#pragma unroll
        for (int k = 0; k < 6; k++) {
            const int row = w * 32 + mi * 16 + ((grp & 1) ? 8 : 0) + lr;
            const int col = k * 16 + ((grp & 2) ? 8 : 0);
            ldsm_x4(qa[mi][k][0], qa[mi][k][1], qa[mi][k][2], qa[mi][k][3],
                    smem_u32(&Qs[row * 104 + col]));
        }

    float oc[2][12][4];
#pragma unroll
    for (int mi = 0; mi < 2; mi++)
#pragma unroll
        for (int j = 0; j < 12; j++)
#pragma unroll
            for (int e = 0; e < 4; e++) oc[mi][j][e] = 0.f;
    float mst[4] = {-3e38f, -3e38f, -3e38f, -3e38f};
    float lst[4] = {0.f, 0.f, 0.f, 0.f};

    const int wrow_max = q0 + w * 32 + 31;   // last row this warp owns
    const int nch = 2 * qt + 2;              // 64-key chunks covering [0, q0+128)

    for (int jc = 0; jc < nch; ++jc) {
        const int kb = jc * 64;
        __syncthreads();

        // ---- load K/V chunk (64 rows each) ----
#pragma unroll
        for (int i = 0; i < 6; i++) {
            const int idx = i * 128 + tid;
            const int row = idx / 12, c = (idx % 12) * 8;
            const __half* base = qkv + (size_t)(b * TSEQ + kb + row) * 2304 + h * 96 + c;
            *(uint4*)&Ks[row * 104 + c] = *(const uint4*)(base + 768);
            *(uint4*)&Vs[row * 104 + c] = *(const uint4*)(base + 1536);
        }
        __syncthreads();

        if (kb > wrow_max) continue;   // fully masked for this warp

#pragma unroll
        for (int sub = 0; sub < 2; sub++) {
            const int ks0 = kb + sub * 32;
            if (ks0 > wrow_max) continue;

            // ---- S = Q K^T over 32 keys: sc[mi][4 n8][4] ----
            float sc[2][4][4];
#pragma unroll
            for (int mi = 0; mi < 2; mi++)
#pragma unroll
                for (int j = 0; j < 4; j++)
#pragma unroll
                    for (int e = 0; e < 4; e++) sc[mi][j][e] = 0.f;
#pragma unroll
            for (int k = 0; k < 6; k++) {
#pragma unroll
                for (int jn = 0; jn < 2; jn++) {
                    const int key = sub * 32 + jn * 16 + lr + ((grp & 2) ? 8 : 0);
                    const int hd  = k * 16 + ((grp & 1) ? 8 : 0);
                    uint32_t b0, b1, b2, b3;
                    ldsm_x4(b0, b1, b2, b3, smem_u32(&Ks[key * 104 + hd]));
#pragma unroll
                    for (int mi = 0; mi < 2; mi++) {
                        mma16816(sc[mi][2 * jn],     qa[mi][k], b0, b1);
                        mma16816(sc[mi][2 * jn + 1], qa[mi][k], b2, b3);
                    }
                }
            }

            // ---- mask + scale + online softmax + pack P ----
            uint32_t pa[2][2][4];
            const bool diag = (ks0 + 31 > q0 + w * 32);  // any col may exceed some row
#pragma unroll
            for (int mi = 0; mi < 2; mi++) {
                const int rA = q0 + w * 32 + mi * 16 + g;
                const int rB = rA + 8;
                float mlocA = -3e38f, mlocB = -3e38f;
#pragma unroll
                for (int j = 0; j < 4; j++) {
                    const int c0 = ks0 + j * 8 + q4 * 2;
                    sc[mi][j][0] *= scale; sc[mi][j][1] *= scale;
                    sc[mi][j][2] *= scale; sc[mi][j][3] *= scale;
                    if (diag) {
                        if (c0     > rA) sc[mi][j][0] = -3e38f;
                        if (c0 + 1 > rA) sc[mi][j][1] = -3e38f;
                        if (c0     > rB) sc[mi][j][2] = -3e38f;
                        if (c0 + 1 > rB) sc[mi][j][3] = -3e38f;
                    }
                    mlocA = fmaxf(mlocA, fmaxf(sc[mi][j][0], sc[mi][j][1]));
                    mlocB = fmaxf(mlocB, fmaxf(sc[mi][j][2], sc[mi][j][3]));
                }
                mlocA = fmaxf(mlocA, __shfl_xor_sync(0xffffffffu, mlocA, 1));
                mlocA = fmaxf(mlocA, __shfl_xor_sync(0xffffffffu, mlocA, 2));
                mlocB = fmaxf(mlocB, __shfl_xor_sync(0xffffffffu, mlocB, 1));
                mlocB = fmaxf(mlocB, __shfl_xor_sync(0xffffffffu, mlocB, 2));
                const float mAn = fmaxf(mst[mi * 2],     mlocA);
                const float mBn = fmaxf(mst[mi * 2 + 1], mlocB);
                const float fA = __expf(mst[mi * 2]     - mAn);
                const float fB = __expf(mst[mi * 2 + 1] - mBn);
                mst[mi * 2] = mAn; mst[mi * 2 + 1] = mBn;

                float lsA = 0.f, lsB = 0.f;
#pragma unroll
                for (int k = 0; k < 2; k++) {
                    const float pA0 = __expf(sc[mi][2 * k][0] - mAn);
                    const float pA1 = __expf(sc[mi][2 * k][1] - mAn);
                    const float pB0 = __expf(sc[mi][2 * k][2] - mBn);
                    const float pB1 = __expf(sc[mi][2 * k][3] - mBn);
                    const float pA2 = __expf(sc[mi][2 * k + 1][0] - mAn);
                    const float pA3 = __expf(sc[mi][2 * k + 1][1] - mAn);
                    const float pB2 = __expf(sc[mi][2 * k + 1][2] - mBn);
                    const float pB3 = __expf(sc[mi][2 * k + 1][3] - mBn);
                    lsA += pA0 + pA1 + pA2 + pA3;
                    lsB += pB0 + pB1 + pB2 + pB3;
                    pa[mi][k][0] = packh2(pA0, pA1);
                    pa[mi][k][1] = packh2(pB0, pB1);
                    pa[mi][k][2] = packh2(pA2, pA3);
                    pa[mi][k][3] = packh2(pB2, pB3);
                }
                lsA += __shfl_xor_sync(0xffffffffu, lsA, 1);
                lsA += __shfl_xor_sync(0xffffffffu, lsA, 2);
                lsB += __shfl_xor_sync(0xffffffffu, lsB, 1);
                lsB += __shfl_xor_sync(0xffffffffu, lsB, 2);
                lst[mi * 2]     = lst[mi * 2]     * fA + lsA;
                lst[mi * 2 + 1] = lst[mi * 2 + 1] * fB + lsB;

#pragma unroll
                for (int j = 0; j < 12; j++) {
                    oc[mi][j][0] *= fA; oc[mi][j][1] *= fA;
                    oc[mi][j][2] *= fB; oc[mi][j][3] *= fB;
                }
            }

            // ---- O += P V over 32 keys ----
#pragma unroll
            for (int n = 0; n < 6; n++) {
#pragma unroll
                for (int k = 0; k < 2; k++) {
                    const int key = sub * 32 + k * 16 + lr + ((grp & 1) ? 8 : 0);
                    const int hd  = n * 16 + ((grp & 2) ? 8 : 0);
                    uint32_t b0, b1, b2, b3;
                    ldsm_x4_t(b0, b1, b2, b3, smem_u32(&Vs[key * 104 + hd]));
#pragma unroll
                    for (int mi = 0; mi < 2; mi++) {
                        mma16816(oc[mi][2 * n],     pa[mi][k], b0, b1);
                        mma16816(oc[mi][2 * n + 1], pa[mi][k], b2, b3);
                    }
                }
            }
        }
    }

    // ---- write y = O / l ----
#pragma unroll
    for (int mi = 0; mi < 2; mi++) {
        const int rA = q0 + w * 32 + mi * 16 + g;
        const int rB = rA + 8;
        const float invA = 1.0f / lst[mi * 2];
        const float invB = 1.0f / lst[mi * 2 + 1];
        __half* yA = y + (size_t)(b * TSEQ + rA) * 768 + h * 96;
        __half* yB = y + (size_t)(b * TSEQ + rB) * 768 + h * 96;
#pragma unroll
        for (int j = 0; j < 12; j++) {
            const int col = j * 8 + q4 * 2;
            *(uint32_t*)(yA + col) = packh2(oc[mi][j][0] * invA, oc[mi][j][1] * invA);
            *(uint32_t*)(yB + col) = packh2(oc[mi][j][2] * invB, oc[mi][j][3] * invB);
        }
    }
}

// ================= launch =================
extern "C" void kernel_launch(void* const* d_in, const int* in_sizes, int n_in,
                              void* d_out, int out_size)
{
    const float* x      = (const float*)d_in[0];
    const float* ln1_g  = (const float*)d_in[1];
    const float* ln1_b  = (const float*)d_in[2];
    const float* attn_w = (const float*)d_in[3];
    const float* attn_b = (const float*)d_in[4];
    const float* proj_w = (const float*)d_in[5];
    const float* proj_b = (const float*)d_in[6];
    const float* ln2_g  = (const float*)d_in[7];
    const float* ln2_b  = (const float*)d_in[8];
    const float* fc_w   = (const float*)d_in[9];
    const float* fc_b   = (const float*)d_in[10];
    const float* fc2_w  = (const float*)d_in[11];
    const float* fc2_b  = (const float*)d_in[12];
    float* out = (float*)d_out;

    __half *h, *qkv, *y, *h2, *wqkv, *wproj, *wfc, *wfc2;
    float *x1;
    cudaGetSymbolAddress((void**)&h,    g_h);
    cudaGetSymbolAddress((void**)&qkv,  g_qkv);
    cudaGetSymbolAddress((void**)&y,    g_y);
    cudaGetSymbolAddress((void**)&x1,   g_x1);
    cudaGetSymbolAddress((void**)&h2,   g_h2);
    cudaGetSymbolAddress((void**)&wqkv, g_wqkv);
    cudaGetSymbolAddress((void**)&wproj,g_wproj);
    cudaGetSymbolAddress((void**)&wfc,  g_wfc);
    cudaGetSymbolAddress((void**)&wfc2, g_wfc2);

    static bool attr_set = false;
    if (!attr_set) {
        cudaFuncSetAttribute(attn_kernel, cudaFuncAttributeMaxDynamicSharedMemorySize, ATTN_SMEM);
        cudaFuncSetAttribute(hgemm_kernel<0>, cudaFuncAttributeMaxDynamicSharedMemorySize, GEMM_SMEM);
        cudaFuncSetAttribute(hgemm_kernel<1>, cudaFuncAttributeMaxDynamicSharedMemorySize, GEMM_SMEM);
        cudaFuncSetAttribute(hgemm_kernel<2>, cudaFuncAttributeMaxDynamicSharedMemorySize, GEMM_SMEM);
        attr_set = true;
    }

    const int n0 = CDIM * 3 * CDIM / 4, n1 = CDIM * CDIM / 4;
    const int n2 = CDIM * 4 * CDIM / 4, n3 = 4 * CDIM * CDIM / 4;
    wconv4_kernel<<<(n0 + n1 + n2 + n3 + 255) / 256, 256>>>(
        attn_w, wqkv, n0, proj_w, wproj, n1, fc_w, wfc, n2, fc2_w, wfc2, n3);

    ln_kernel<<<MTOK, 256>>>(x, ln1_g, ln1_b, h);
    hgemm_kernel<0><<<dim3(2304 / 128, MTOK / 128), 128, GEMM_SMEM>>>(
        h, wqkv, attn_b, nullptr, nullptr, qkv, 2304, 768);
    attn_kernel<<<dim3(TSEQ / 128, NHEAD, BATCH), 128, ATTN_SMEM>>>(qkv, y);
    hgemm_kernel<1><<<dim3(768 / 128, MTOK / 128), 128, GEMM_SMEM>>>(
        y, wproj, proj_b, x, x1, nullptr, 768, 768);
    ln_kernel<<<MTOK, 256>>>(x1, ln2_g, ln2_b, h);
    hgemm_kernel<2><<<dim3(3072 / 128, MTOK / 128), 128, GEMM_SMEM>>>(
        h, wfc, fc_b, nullptr, nullptr, h2, 3072, 768);
    hgemm_kernel<1><<<dim3(768 / 128, MTOK / 128), 128, GEMM_SMEM>>>(
        h2, wfc2, fc2_b, x1, out, nullptr, 768, 3072);
}